// round 7
// baseline (speedup 1.0000x reference)
#include <cuda_runtime.h>

#define NN 100000
#define DH 128
#define NE 1600000
#define BN_EPS 1e-5f

// ---------------- scratch (device globals; no allocation allowed) ----------------
// Two big buffers only (102 MB total):
//   g_buf: GEMM1 output -> (in-place MODE1) gather source relu(h)*norm_src
//   g_agg: scatter-add target / prop-GEMM input
__device__ __align__(128) float g_buf[NN * DH];
__device__ __align__(128) float g_agg[NN * DH];
__device__ float g_norm_src[NN];
__device__ float g_norm_dst[NN];
__device__ int   g_outdeg[NN];
__device__ int   g_indeg[NN];
__device__ float g_colsum[DH];
__device__ float g_colsq[DH];
__device__ float g_scale[DH];
__device__ float g_shift[DH];

// ---------------- small utility kernels ----------------
__global__ void k_zero_misc() {
    int i = blockIdx.x * blockDim.x + threadIdx.x;
    if (i < NN) { g_outdeg[i] = 0; g_indeg[i] = 0; }
    if (i < DH) { g_colsum[i] = 0.f; g_colsq[i] = 0.f; }
}

__global__ void k_degcount(const int* __restrict__ src, const int* __restrict__ dst) {
    int i = blockIdx.x * blockDim.x + threadIdx.x;
    if (i < NE) {
        atomicAdd(&g_outdeg[src[i]], 1);
        atomicAdd(&g_indeg[dst[i]], 1);
    }
}

__global__ void k_norms() {
    int i = blockIdx.x * blockDim.x + threadIdx.x;
    if (i < NN) {
        g_norm_src[i] = rsqrtf(fmaxf((float)g_outdeg[i], 1.0f));
        g_norm_dst[i] = rsqrtf(fmaxf((float)g_indeg[i], 1.0f));
    }
}

// per-column sum / sum-of-squares over g_buf (BN batch stats)
__global__ void k_colreduce() {
    int c = threadIdx.x;  // 128 threads
    float s = 0.f, sq = 0.f;
    for (int r = blockIdx.x; r < NN; r += gridDim.x) {
        float v = g_buf[r * DH + c];
        s += v;
        sq += v * v;
    }
    atomicAdd(&g_colsum[c], s);
    atomicAdd(&g_colsq[c], sq);
}

__global__ void k_bnfin(const float* __restrict__ gamma, const float* __restrict__ beta) {
    int c = threadIdx.x;  // 128 threads
    float mu  = g_colsum[c] * (1.0f / NN);
    float var = g_colsq[c] * (1.0f / NN) - mu * mu;
    float inv = rsqrtf(var + BN_EPS);
    float sc  = gamma[c] * inv;
    g_scale[c] = sc;
    g_shift[c] = beta[c] - mu * sc;
}

__global__ void k_zero_agg() {
    int i = blockIdx.x * blockDim.x + threadIdx.x;
    if (i < NN * DH / 4) ((float4*)g_agg)[i] = make_float4(0.f, 0.f, 0.f, 0.f);
}

// ---------------- edge gather + vector-red scatter ----------------
// one warp per edge; lane handles 4 consecutive floats (float4)
__global__ void k_edge_scatter(const int* __restrict__ src, const int* __restrict__ dst) {
    int gtid   = blockIdx.x * blockDim.x + threadIdx.x;
    int nwarps = (gridDim.x * blockDim.x) >> 5;
    int loff   = (threadIdx.x & 31) * 4;
    for (int e = gtid >> 5; e < NE; e += nwarps) {
        int s = __ldg(&src[e]);
        int d = __ldg(&dst[e]);
        float4 v = *(const float4*)&g_buf[s * DH + loff];
        float* p = &g_agg[d * DH + loff];
        asm volatile("red.global.add.v4.f32 [%0], {%1, %2, %3, %4};"
                     :: "l"(p), "f"(v.x), "f"(v.y), "f"(v.z), "f"(v.w)
                     : "memory");
    }
}

// ---------------- fused GEMM (M x 128 @ 128 x 128), tile 64x128, K-chunk 32 ----------------
// MODE 0: out = A@B + bias                                  A=in_feat  -> g_buf
// MODE 1: A'=relu(A*scale_k+shift_k); out=relu(A'@B+bias)*norm_src[r]  A=g_buf -> g_buf (IN-PLACE:
//         each block reads only its own 64 rows during the k-loop and writes them after)
// MODE 2: out = relu((A@B)*norm_dst[r] + bias) * norm_src[r]  A=g_agg -> g_buf
// MODE 3: out = (A@B)*norm_dst[r] + bias                      A=g_agg -> d_out
template <int MODE>
__global__ void __launch_bounds__(256) k_gemm(const float* __restrict__ Ain,
                                              const float* __restrict__ B,
                                              const float* __restrict__ bias,
                                              float* __restrict__ Oout) {
    __shared__ float As[64][32];
    __shared__ float Bs[32][128];

    const float* A = (MODE == 0) ? Ain : (MODE == 1 ? g_buf : g_agg);
    float* O       = (MODE == 3) ? Oout : g_buf;

    int tid  = threadIdx.x;
    int cx   = tid & 31;   // column group: cols cx*4 .. cx*4+3
    int ry   = tid >> 5;   // row group: rows ry*8 .. ry*8+7
    int row0 = blockIdx.x * 64;

    float4 acc[8];
#pragma unroll
    for (int i = 0; i < 8; i++) acc[i] = make_float4(0.f, 0.f, 0.f, 0.f);

    for (int k0 = 0; k0 < DH; k0 += 32) {
        // load A tile: 64x32 = 512 float4; thread handles f = tid*2, tid*2+1
#pragma unroll
        for (int t = 0; t < 2; t++) {
            int f  = tid * 2 + t;
            int r  = f >> 3;     // 0..63
            int kc = f & 7;      // 0..7 (float4 along k)
            int gr = row0 + r;
            float4 a = (gr < NN) ? *(const float4*)&A[gr * DH + k0 + kc * 4]
                                 : make_float4(0.f, 0.f, 0.f, 0.f);
            if (MODE == 1) {
                float4 sc = *(const float4*)&g_scale[k0 + kc * 4];
                float4 sh = *(const float4*)&g_shift[k0 + kc * 4];
                a.x = fmaxf(fmaf(a.x, sc.x, sh.x), 0.f);
                a.y = fmaxf(fmaf(a.y, sc.y, sh.y), 0.f);
                a.z = fmaxf(fmaf(a.z, sc.z, sh.z), 0.f);
                a.w = fmaxf(fmaf(a.w, sc.w, sh.w), 0.f);
            }
            *(float4*)&As[r][kc * 4] = a;
        }
        // load B tile: 32x128 = 1024 float4; thread handles f = tid*4 .. +3
#pragma unroll
        for (int t = 0; t < 4; t++) {
            int f  = tid * 4 + t;
            int r  = f >> 5;     // 0..31
            int c4 = f & 31;     // 0..31
            *(float4*)&Bs[r][c4 * 4] = *(const float4*)&B[(k0 + r) * DH + c4 * 4];
        }
        __syncthreads();

#pragma unroll
        for (int kk = 0; kk < 32; kk++) {
            float4 b = *(float4*)&Bs[kk][cx * 4];
#pragma unroll
            for (int i = 0; i < 8; i++) {
                float a = As[ry * 8 + i][kk];
                acc[i].x = fmaf(a, b.x, acc[i].x);
                acc[i].y = fmaf(a, b.y, acc[i].y);
                acc[i].z = fmaf(a, b.z, acc[i].z);
                acc[i].w = fmaf(a, b.w, acc[i].w);
            }
        }
        __syncthreads();
    }

    float4 bv = *(const float4*)&bias[cx * 4];
#pragma unroll
    for (int i = 0; i < 8; i++) {
        int r = row0 + ry * 8 + i;
        if (r >= NN) break;
        float4 v = acc[i];
        if (MODE == 0) {
            v.x += bv.x; v.y += bv.y; v.z += bv.z; v.w += bv.w;
        } else if (MODE == 1) {
            float ns = g_norm_src[r];
            v.x = fmaxf(v.x + bv.x, 0.f) * ns;
            v.y = fmaxf(v.y + bv.y, 0.f) * ns;
            v.z = fmaxf(v.z + bv.z, 0.f) * ns;
            v.w = fmaxf(v.w + bv.w, 0.f) * ns;
        } else if (MODE == 2) {
            float nd = g_norm_dst[r];
            float ns = g_norm_src[r];
            v.x = fmaxf(fmaf(v.x, nd, bv.x), 0.f) * ns;
            v.y = fmaxf(fmaf(v.y, nd, bv.y), 0.f) * ns;
            v.z = fmaxf(fmaf(v.z, nd, bv.z), 0.f) * ns;
            v.w = fmaxf(fmaf(v.w, nd, bv.w), 0.f) * ns;
        } else {  // MODE 3
            float nd = g_norm_dst[r];
            v.x = fmaf(v.x, nd, bv.x);
            v.y = fmaf(v.y, nd, bv.y);
            v.z = fmaf(v.z, nd, bv.z);
            v.w = fmaf(v.w, nd, bv.w);
        }
        *(float4*)&O[r * DH + cx * 4] = v;
    }
}

// ---------------- launch ----------------
extern "C" void kernel_launch(void* const* d_in, const int* in_sizes, int n_in,
                              void* d_out, int out_size) {
    const float* in_feat = (const float*)d_in[0];
    const int*   src     = (const int*)d_in[1];
    const int*   dst     = (const int*)d_in[2];
    const float* W1      = (const float*)d_in[3];
    const float* b1      = (const float*)d_in[4];
    const float* gamma   = (const float*)d_in[5];
    const float* beta    = (const float*)d_in[6];
    const float* W2      = (const float*)d_in[7];
    const float* b2      = (const float*)d_in[8];
    const float* Wc      = (const float*)d_in[9];
    const float* bc      = (const float*)d_in[10];
    float* out = (float*)d_out;

    const int GEMM_GRID = (NN + 63) / 64;  // 1563

    // degrees + norms (must re-zero every replay)
    k_zero_misc<<<(NN + 255) / 256, 256>>>();
    k_degcount<<<(NE + 255) / 256, 256>>>(src, dst);
    k_norms<<<(NN + 255) / 256, 256>>>();

    // MLP: GEMM1 -> BN stats -> BN finalize -> GEMM2 (BN+ReLU fused on A, relu*norm_src epilogue, in-place)
    k_gemm<0><<<GEMM_GRID, 256>>>(in_feat, W1, b1, nullptr);
    k_colreduce<<<512, DH>>>();
    k_bnfin<<<1, DH>>>(gamma, beta);
    k_gemm<1><<<GEMM_GRID, 256>>>(nullptr, W2, b2, nullptr);

    // 3 propagation steps
    for (int s = 0; s < 3; s++) {
        k_zero_agg<<<(NN * DH / 4 + 255) / 256, 256>>>();
        k_edge_scatter<<<4736, 256>>>(src, dst);
        if (s < 2)
            k_gemm<2><<<GEMM_GRID, 256>>>(nullptr, Wc, bc, nullptr);
        else
            k_gemm<3><<<GEMM_GRID, 256>>>(nullptr, Wc, bc, out);
    }
}

// round 9
// speedup vs baseline: 1.1025x; 1.1025x over previous
#include <cuda_runtime.h>

#define NN 100000
#define DH 128
#define NE 1600000
#define BN_EPS 1e-5f

// ---------------- scratch (device globals; no allocation allowed) ----------------
//   g_buf: GEMM1 output -> (in-place MODE1) gather source relu(h)*norm_src
//   g_agg: scatter-add target / prop-GEMM input
__device__ __align__(128) float g_buf[NN * DH];
__device__ __align__(128) float g_agg[NN * DH];
__device__ float g_norm_src[NN];
__device__ float g_norm_dst[NN];
__device__ int   g_outdeg[NN];
__device__ int   g_indeg[NN];
__device__ float g_colsum[DH];
__device__ float g_colsq[DH];
__device__ float g_scale[DH];
__device__ float g_shift[DH];

// ---------------- small utility kernels ----------------
__global__ void k_zero_misc() {
    int i = blockIdx.x * blockDim.x + threadIdx.x;
    if (i < NN) { g_outdeg[i] = 0; g_indeg[i] = 0; }
    if (i < DH) { g_colsum[i] = 0.f; g_colsq[i] = 0.f; }
}

__global__ void k_degcount(const int* __restrict__ src, const int* __restrict__ dst) {
    int i = blockIdx.x * blockDim.x + threadIdx.x;
    if (i < NE) {
        atomicAdd(&g_outdeg[src[i]], 1);
        atomicAdd(&g_indeg[dst[i]], 1);
    }
}

__global__ void k_norms() {
    int i = blockIdx.x * blockDim.x + threadIdx.x;
    if (i < NN) {
        g_norm_src[i] = rsqrtf(fmaxf((float)g_outdeg[i], 1.0f));
        g_norm_dst[i] = rsqrtf(fmaxf((float)g_indeg[i], 1.0f));
    }
}

// per-column sum / sum-of-squares over g_buf (BN batch stats)
__global__ void k_colreduce() {
    int c = threadIdx.x;  // 128 threads
    float s = 0.f, sq = 0.f;
    for (int r = blockIdx.x; r < NN; r += gridDim.x) {
        float v = g_buf[r * DH + c];
        s += v;
        sq += v * v;
    }
    atomicAdd(&g_colsum[c], s);
    atomicAdd(&g_colsq[c], sq);
}

__global__ void k_bnfin(const float* __restrict__ gamma, const float* __restrict__ beta) {
    int c = threadIdx.x;  // 128 threads
    float mu  = g_colsum[c] * (1.0f / NN);
    float var = g_colsq[c] * (1.0f / NN) - mu * mu;
    float inv = rsqrtf(var + BN_EPS);
    float sc  = gamma[c] * inv;
    g_scale[c] = sc;
    g_shift[c] = beta[c] - mu * sc;
}

// ---------------- edge gather + vector-red scatter ----------------
// one warp per edge; lane handles 4 consecutive floats (float4)
__global__ void k_edge_scatter(const int* __restrict__ src, const int* __restrict__ dst) {
    int gtid   = blockIdx.x * blockDim.x + threadIdx.x;
    int nwarps = (gridDim.x * blockDim.x) >> 5;
    int loff   = (threadIdx.x & 31) * 4;
    for (int e = gtid >> 5; e < NE; e += nwarps) {
        int s = __ldg(&src[e]);
        int d = __ldg(&dst[e]);
        float4 v = *(const float4*)&g_buf[s * DH + loff];
        float* p = &g_agg[d * DH + loff];
        asm volatile("red.global.add.v4.f32 [%0], {%1, %2, %3, %4};"
                     :: "l"(p), "f"(v.x), "f"(v.y), "f"(v.z), "f"(v.w)
                     : "memory");
    }
}

// ---------------- fused GEMM (M x 128 @ 128 x 128), tile 128x128, K-chunk 32 ----------------
// 256 threads, 8x8 micro-tile per thread; A transposed in SMEM for vector LDS.
// MODE 0: out = A@B + bias                                  A=in_feat  -> g_buf
// MODE 1: A'=relu(A*scale_k+shift_k); out=relu(A'@B+bias)*norm_src[r]  A=g_buf -> g_buf (IN-PLACE:
//         each block reads only its own 128 rows during the k-loop and writes them after).
//         Epilogue also zeroes this block's rows of g_agg (prep for next scatter).
// MODE 2: out = relu((A@B)*norm_dst[r] + bias) * norm_src[r]  A=g_agg -> g_buf ; zero own g_agg rows
// MODE 3: out = (A@B)*norm_dst[r] + bias                      A=g_agg -> d_out (no zeroing)
template <int MODE>
__global__ void __launch_bounds__(256, 2) k_gemm(const float* __restrict__ Ain,
                                                 const float* __restrict__ B,
                                                 const float* __restrict__ bias,
                                                 float* __restrict__ Oout) {
    __shared__ float AsT[32][132];   // [k][row], padded to 132 to spread banks
    __shared__ float Bs[32][128];

    const float* A = (MODE == 0) ? Ain : (MODE == 1 ? g_buf : g_agg);
    float* O       = (MODE == 3) ? Oout : g_buf;

    int tid  = threadIdx.x;
    int tx   = tid & 15;   // col group: cols tx*4..+3 and tx*4+64..+67
    int ty   = tid >> 4;   // row group: rows ty*8..+7
    int row0 = blockIdx.x * 128;

    float acc[8][8];
#pragma unroll
    for (int i = 0; i < 8; i++)
#pragma unroll
        for (int j = 0; j < 8; j++) acc[i][j] = 0.f;

    for (int k0 = 0; k0 < DH; k0 += 32) {
        // A tile: 128 rows x 32 k = 1024 float4-equivalents... 1024 float4? (128*32/4=1024)
        // f = t*256 + tid; r = f>>3 (0..127), k4 = f&7 (float4 index along k)
#pragma unroll
        for (int t = 0; t < 4; t++) {
            int f  = t * 256 + tid;
            int r  = f >> 3;
            int k4 = f & 7;
            int gr = row0 + r;
            float4 a = (gr < NN) ? *(const float4*)&A[gr * DH + k0 + k4 * 4]
                                 : make_float4(0.f, 0.f, 0.f, 0.f);
            if (MODE == 1) {
                float4 sc = *(const float4*)&g_scale[k0 + k4 * 4];
                float4 sh = *(const float4*)&g_shift[k0 + k4 * 4];
                a.x = fmaxf(fmaf(a.x, sc.x, sh.x), 0.f);
                a.y = fmaxf(fmaf(a.y, sc.y, sh.y), 0.f);
                a.z = fmaxf(fmaf(a.z, sc.z, sh.z), 0.f);
                a.w = fmaxf(fmaf(a.w, sc.w, sh.w), 0.f);
            }
            AsT[k4 * 4 + 0][r] = a.x;
            AsT[k4 * 4 + 1][r] = a.y;
            AsT[k4 * 4 + 2][r] = a.z;
            AsT[k4 * 4 + 3][r] = a.w;
        }
        // B tile: 32 x 128 = 1024 float4; f = t*256 + tid; r = f>>5, c4 = f&31
#pragma unroll
        for (int t = 0; t < 4; t++) {
            int f  = t * 256 + tid;
            int r  = f >> 5;
            int c4 = f & 31;
            *(float4*)&Bs[r][c4 * 4] = *(const float4*)&B[(k0 + r) * DH + c4 * 4];
        }
        __syncthreads();

#pragma unroll
        for (int kk = 0; kk < 32; kk++) {
            float4 a0 = *(float4*)&AsT[kk][ty * 8];
            float4 a1 = *(float4*)&AsT[kk][ty * 8 + 4];
            float4 b0 = *(float4*)&Bs[kk][tx * 4];
            float4 b1 = *(float4*)&Bs[kk][tx * 4 + 64];
            float av[8] = {a0.x, a0.y, a0.z, a0.w, a1.x, a1.y, a1.z, a1.w};
            float bv[8] = {b0.x, b0.y, b0.z, b0.w, b1.x, b1.y, b1.z, b1.w};
#pragma unroll
            for (int i = 0; i < 8; i++)
#pragma unroll
                for (int j = 0; j < 8; j++)
                    acc[i][j] = fmaf(av[i], bv[j], acc[i][j]);
        }
        __syncthreads();
    }

    float4 bv0 = *(const float4*)&bias[tx * 4];
    float4 bv1 = *(const float4*)&bias[tx * 4 + 64];
#pragma unroll
    for (int i = 0; i < 8; i++) {
        int r = row0 + ty * 8 + i;
        if (r >= NN) break;
        float4 v0 = make_float4(acc[i][0], acc[i][1], acc[i][2], acc[i][3]);
        float4 v1 = make_float4(acc[i][4], acc[i][5], acc[i][6], acc[i][7]);
        if (MODE == 0) {
            v0.x += bv0.x; v0.y += bv0.y; v0.z += bv0.z; v0.w += bv0.w;
            v1.x += bv1.x; v1.y += bv1.y; v1.z += bv1.z; v1.w += bv1.w;
        } else if (MODE == 1) {
            float ns = g_norm_src[r];
            v0.x = fmaxf(v0.x + bv0.x, 0.f) * ns;
            v0.y = fmaxf(v0.y + bv0.y, 0.f) * ns;
            v0.z = fmaxf(v0.z + bv0.z, 0.f) * ns;
            v0.w = fmaxf(v0.w + bv0.w, 0.f) * ns;
            v1.x = fmaxf(v1.x + bv1.x, 0.f) * ns;
            v1.y = fmaxf(v1.y + bv1.y, 0.f) * ns;
            v1.z = fmaxf(v1.z + bv1.z, 0.f) * ns;
            v1.w = fmaxf(v1.w + bv1.w, 0.f) * ns;
        } else if (MODE == 2) {
            float nd = g_norm_dst[r];
            float ns = g_norm_src[r];
            v0.x = fmaxf(fmaf(v0.x, nd, bv0.x), 0.f) * ns;
            v0.y = fmaxf(fmaf(v0.y, nd, bv0.y), 0.f) * ns;
            v0.z = fmaxf(fmaf(v0.z, nd, bv0.z), 0.f) * ns;
            v0.w = fmaxf(fmaf(v0.w, nd, bv0.w), 0.f) * ns;
            v1.x = fmaxf(fmaf(v1.x, nd, bv1.x), 0.f) * ns;
            v1.y = fmaxf(fmaf(v1.y, nd, bv1.y), 0.f) * ns;
            v1.z = fmaxf(fmaf(v1.z, nd, bv1.z), 0.f) * ns;
            v1.w = fmaxf(fmaf(v1.w, nd, bv1.w), 0.f) * ns;
        } else {  // MODE 3
            float nd = g_norm_dst[r];
            v0.x = fmaf(v0.x, nd, bv0.x);
            v0.y = fmaf(v0.y, nd, bv0.y);
            v0.z = fmaf(v0.z, nd, bv0.z);
            v0.w = fmaf(v0.w, nd, bv0.w);
            v1.x = fmaf(v1.x, nd, bv1.x);
            v1.y = fmaf(v1.y, nd, bv1.y);
            v1.z = fmaf(v1.z, nd, bv1.z);
            v1.w = fmaf(v1.w, nd, bv1.w);
        }
        *(float4*)&O[r * DH + tx * 4]      = v0;
        *(float4*)&O[r * DH + tx * 4 + 64] = v1;
        if (MODE == 1 || MODE == 2) {
            // zero this block's g_agg rows for the NEXT edge scatter (block-exclusive rows)
            float4 z = make_float4(0.f, 0.f, 0.f, 0.f);
            *(float4*)&g_agg[r * DH + tx * 4]      = z;
            *(float4*)&g_agg[r * DH + tx * 4 + 64] = z;
        }
    }
}

// ---------------- launch ----------------
extern "C" void kernel_launch(void* const* d_in, const int* in_sizes, int n_in,
                              void* d_out, int out_size) {
    const float* in_feat = (const float*)d_in[0];
    const int*   src     = (const int*)d_in[1];
    const int*   dst     = (const int*)d_in[2];
    const float* W1      = (const float*)d_in[3];
    const float* b1      = (const float*)d_in[4];
    const float* gamma   = (const float*)d_in[5];
    const float* beta    = (const float*)d_in[6];
    const float* W2      = (const float*)d_in[7];
    const float* b2      = (const float*)d_in[8];
    const float* Wc      = (const float*)d_in[9];
    const float* bc      = (const float*)d_in[10];
    float* out = (float*)d_out;

    const int GEMM_GRID = (NN + 127) / 128;  // 782

    // degrees + norms (must re-zero every replay)
    k_zero_misc<<<(NN + 255) / 256, 256>>>();
    k_degcount<<<(NE + 255) / 256, 256>>>(src, dst);
    k_norms<<<(NN + 255) / 256, 256>>>();

    // MLP: GEMM1 -> BN stats -> BN finalize -> GEMM2 (BN+ReLU fused on A, relu*norm_src
    // epilogue, in-place; epilogue zeroes g_agg for first scatter)
    k_gemm<0><<<GEMM_GRID, 256>>>(in_feat, W1, b1, nullptr);
    k_colreduce<<<512, DH>>>();
    k_bnfin<<<1, DH>>>(gamma, beta);
    k_gemm<1><<<GEMM_GRID, 256>>>(nullptr, W2, b2, nullptr);

    // 3 propagation steps; MODE2 epilogue re-zeroes g_agg for the next scatter
    for (int s = 0; s < 3; s++) {
        k_edge_scatter<<<4736, 256>>>(src, dst);
        if (s < 2)
            k_gemm<2><<<GEMM_GRID, 256>>>(nullptr, Wc, bc, nullptr);
        else
            k_gemm<3><<<GEMM_GRID, 256>>>(nullptr, Wc, bc, out);
    }
}

// round 12
// speedup vs baseline: 1.5432x; 1.3997x over previous
#include <cuda_runtime.h>

#define NN 100000
#define DH 128
#define NE 1600000
#define BN_EPS 1e-5f
#define SLOTS 48
#define OVF_CAP 8192

// ---------------- scratch (device globals; no allocation allowed) ----------------
//   g_buf: GEMM1 output -> (in-place MODE1) gather source relu(h)*norm_src
//   g_agg: gather output / prop-GEMM input
//   g_slot: per-dst-node list of src ids (SLOTS slots/node), built once per launch
__device__ __align__(128) float g_buf[NN * DH];
__device__ __align__(128) float g_agg[NN * DH];
__device__ __align__(128) int   g_slot[NN * SLOTS];
__device__ int   g_pos[NN];       // in-degree counter / slot cursor
__device__ int   g_outdeg[NN];
__device__ float g_norm_src[NN];
__device__ float g_norm_dst[NN];
__device__ float g_colsum[DH];
__device__ float g_colsq[DH];
__device__ float g_scale[DH];
__device__ float g_shift[DH];
__device__ int   g_ovf[OVF_CAP];
__device__ int   g_n_ovf;

// ---------------- small utility kernels ----------------
__global__ void k_zero() {
    int i = blockIdx.x * blockDim.x + threadIdx.x;
    if (i < NN) { g_outdeg[i] = 0; g_pos[i] = 0; }
    if (i < DH) { g_colsum[i] = 0.f; g_colsq[i] = 0.f; }
    if (i == 0) g_n_ovf = 0;
}

// build per-node src lists (once per launch; edges are constant) + outdeg count
__global__ void k_build(const int* __restrict__ src, const int* __restrict__ dst) {
    int e = blockIdx.x * blockDim.x + threadIdx.x;
    if (e >= NE) return;
    int s = src[e];
    int d = dst[e];
    atomicAdd(&g_outdeg[s], 1);
    int p = atomicAdd(&g_pos[d], 1);
    if (p < SLOTS) {
        g_slot[d * SLOTS + p] = s;
    } else {
        int o = atomicAdd(&g_n_ovf, 1);
        if (o < OVF_CAP) g_ovf[o] = e;
    }
}

__global__ void k_norms() {
    int i = blockIdx.x * blockDim.x + threadIdx.x;
    if (i < NN) {
        g_norm_src[i] = rsqrtf(fmaxf((float)g_outdeg[i], 1.0f));
        g_norm_dst[i] = rsqrtf(fmaxf((float)g_pos[i], 1.0f));  // g_pos == indeg
    }
}

// per-column sum / sum-of-squares over g_buf (BN batch stats)
__global__ void k_colreduce() {
    int c = threadIdx.x;  // 128 threads
    float s = 0.f, sq = 0.f;
    for (int r = blockIdx.x; r < NN; r += gridDim.x) {
        float v = g_buf[r * DH + c];
        s += v;
        sq += v * v;
    }
    atomicAdd(&g_colsum[c], s);
    atomicAdd(&g_colsq[c], sq);
}

__global__ void k_bnfin(const float* __restrict__ gamma, const float* __restrict__ beta) {
    int c = threadIdx.x;  // 128 threads
    float mu  = g_colsum[c] * (1.0f / NN);
    float var = g_colsq[c] * (1.0f / NN) - mu * mu;
    float inv = rsqrtf(var + BN_EPS);
    float sc  = gamma[c] * inv;
    g_scale[c] = sc;
    g_shift[c] = beta[c] - mu * sc;
}

// ---------------- gather: warp per dst node, register accumulation, single store ----------------
__global__ void __launch_bounds__(256) k_gather() {
    int warp = (blockIdx.x * blockDim.x + threadIdx.x) >> 5;
    int lane = threadIdx.x & 31;
    if (warp >= NN) return;
    int n = g_pos[warp];
    if (n > SLOTS) n = SLOTS;
    const int* sl = &g_slot[warp * SLOTS];
    const float* bufl = g_buf + (lane * 4);
    float4 acc = make_float4(0.f, 0.f, 0.f, 0.f);
    int s_next = (n > 0) ? __ldg(&sl[0]) : 0;
    for (int j = 0; j < n; j++) {
        int s = s_next;
        if (j + 1 < n) s_next = __ldg(&sl[j + 1]);   // prefetch next index
        float4 v = *(const float4*)(bufl + s * DH);
        acc.x += v.x; acc.y += v.y; acc.z += v.z; acc.w += v.w;
    }
    *(float4*)&g_agg[warp * DH + lane * 4] = acc;
}

// apply rare overflow edges (deg > SLOTS) with vector reductions; almost always n==0
__global__ void k_ovf(const int* __restrict__ src, const int* __restrict__ dst) {
    int n = g_n_ovf;
    if (n > OVF_CAP) n = OVF_CAP;
    int warp = threadIdx.x >> 5;      // 8 warps, 1 block
    int lane = threadIdx.x & 31;
    int loff = lane * 4;
    for (int i = warp; i < n; i += 8) {
        int e = g_ovf[i];
        int s = __ldg(&src[e]);
        int d = __ldg(&dst[e]);
        float4 v = *(const float4*)&g_buf[s * DH + loff];
        float* p = &g_agg[d * DH + loff];
        asm volatile("red.global.add.v4.f32 [%0], {%1, %2, %3, %4};"
                     :: "l"(p), "f"(v.x), "f"(v.y), "f"(v.z), "f"(v.w)
                     : "memory");
    }
}

// ---------------- fused GEMM (M x 128 @ 128 x 128), tile 128x128, K-chunk 32 ----------------
// 256 threads, 8x8 micro-tile per thread; A transposed in SMEM for vector LDS.
// MODE 0: out = A@B + bias                                  A=in_feat  -> g_buf
// MODE 1: A'=relu(A*scale_k+shift_k); out=relu(A'@B+bias)*norm_src[r]  A=g_buf -> g_buf (IN-PLACE:
//         each block reads only its own 128 rows during the k-loop and writes them after)
// MODE 2: out = relu((A@B)*norm_dst[r] + bias) * norm_src[r]  A=g_agg -> g_buf
// MODE 3: out = (A@B)*norm_dst[r] + bias                      A=g_agg -> d_out
template <int MODE>
__global__ void __launch_bounds__(256, 2) k_gemm(const float* __restrict__ Ain,
                                                 const float* __restrict__ B,
                                                 const float* __restrict__ bias,
                                                 float* __restrict__ Oout) {
    __shared__ float AsT[32][132];   // [k][row], padded to 132 to spread banks
    __shared__ float Bs[32][128];

    const float* A = (MODE == 0) ? Ain : (MODE == 1 ? g_buf : g_agg);
    float* O       = (MODE == 3) ? Oout : g_buf;

    int tid  = threadIdx.x;
    int tx   = tid & 15;   // col group: cols tx*4..+3 and tx*4+64..+67
    int ty   = tid >> 4;   // row group: rows ty*8..+7
    int row0 = blockIdx.x * 128;

    float acc[8][8];
#pragma unroll
    for (int i = 0; i < 8; i++)
#pragma unroll
        for (int j = 0; j < 8; j++) acc[i][j] = 0.f;

    for (int k0 = 0; k0 < DH; k0 += 32) {
        // A tile: 128 rows x 32 k; f = t*256 + tid; r = f>>3 (0..127), k4 = f&7
#pragma unroll
        for (int t = 0; t < 4; t++) {
            int f  = t * 256 + tid;
            int r  = f >> 3;
            int k4 = f & 7;
            int gr = row0 + r;
            float4 a = (gr < NN) ? *(const float4*)&A[gr * DH + k0 + k4 * 4]
                                 : make_float4(0.f, 0.f, 0.f, 0.f);
            if (MODE == 1) {
                float4 sc = *(const float4*)&g_scale[k0 + k4 * 4];
                float4 sh = *(const float4*)&g_shift[k0 + k4 * 4];
                a.x = fmaxf(fmaf(a.x, sc.x, sh.x), 0.f);
                a.y = fmaxf(fmaf(a.y, sc.y, sh.y), 0.f);
                a.z = fmaxf(fmaf(a.z, sc.z, sh.z), 0.f);
                a.w = fmaxf(fmaf(a.w, sc.w, sh.w), 0.f);
            }
            AsT[k4 * 4 + 0][r] = a.x;
            AsT[k4 * 4 + 1][r] = a.y;
            AsT[k4 * 4 + 2][r] = a.z;
            AsT[k4 * 4 + 3][r] = a.w;
        }
        // B tile: 32 x 128; f = t*256 + tid; r = f>>5, c4 = f&31
#pragma unroll
        for (int t = 0; t < 4; t++) {
            int f  = t * 256 + tid;
            int r  = f >> 5;
            int c4 = f & 31;
            *(float4*)&Bs[r][c4 * 4] = *(const float4*)&B[(k0 + r) * DH + c4 * 4];
        }
        __syncthreads();

#pragma unroll
        for (int kk = 0; kk < 32; kk++) {
            float4 a0 = *(float4*)&AsT[kk][ty * 8];
            float4 a1 = *(float4*)&AsT[kk][ty * 8 + 4];
            float4 b0 = *(float4*)&Bs[kk][tx * 4];
            float4 b1 = *(float4*)&Bs[kk][tx * 4 + 64];
            float av[8] = {a0.x, a0.y, a0.z, a0.w, a1.x, a1.y, a1.z, a1.w};
            float bv[8] = {b0.x, b0.y, b0.z, b0.w, b1.x, b1.y, b1.z, b1.w};
#pragma unroll
            for (int i = 0; i < 8; i++)
#pragma unroll
                for (int j = 0; j < 8; j++)
                    acc[i][j] = fmaf(av[i], bv[j], acc[i][j]);
        }
        __syncthreads();
    }

    float4 bv0 = *(const float4*)&bias[tx * 4];
    float4 bv1 = *(const float4*)&bias[tx * 4 + 64];
#pragma unroll
    for (int i = 0; i < 8; i++) {
        int r = row0 + ty * 8 + i;
        if (r >= NN) break;
        float4 v0 = make_float4(acc[i][0], acc[i][1], acc[i][2], acc[i][3]);
        float4 v1 = make_float4(acc[i][4], acc[i][5], acc[i][6], acc[i][7]);
        if (MODE == 0) {
            v0.x += bv0.x; v0.y += bv0.y; v0.z += bv0.z; v0.w += bv0.w;
            v1.x += bv1.x; v1.y += bv1.y; v1.z += bv1.z; v1.w += bv1.w;
        } else if (MODE == 1) {
            float ns = g_norm_src[r];
            v0.x = fmaxf(v0.x + bv0.x, 0.f) * ns;
            v0.y = fmaxf(v0.y + bv0.y, 0.f) * ns;
            v0.z = fmaxf(v0.z + bv0.z, 0.f) * ns;
            v0.w = fmaxf(v0.w + bv0.w, 0.f) * ns;
            v1.x = fmaxf(v1.x + bv1.x, 0.f) * ns;
            v1.y = fmaxf(v1.y + bv1.y, 0.f) * ns;
            v1.z = fmaxf(v1.z + bv1.z, 0.f) * ns;
            v1.w = fmaxf(v1.w + bv1.w, 0.f) * ns;
        } else if (MODE == 2) {
            float nd = g_norm_dst[r];
            float ns = g_norm_src[r];
            v0.x = fmaxf(fmaf(v0.x, nd, bv0.x), 0.f) * ns;
            v0.y = fmaxf(fmaf(v0.y, nd, bv0.y), 0.f) * ns;
            v0.z = fmaxf(fmaf(v0.z, nd, bv0.z), 0.f) * ns;
            v0.w = fmaxf(fmaf(v0.w, nd, bv0.w), 0.f) * ns;
            v1.x = fmaxf(fmaf(v1.x, nd, bv1.x), 0.f) * ns;
            v1.y = fmaxf(fmaf(v1.y, nd, bv1.y), 0.f) * ns;
            v1.z = fmaxf(fmaf(v1.z, nd, bv1.z), 0.f) * ns;
            v1.w = fmaxf(fmaf(v1.w, nd, bv1.w), 0.f) * ns;
        } else {  // MODE 3
            float nd = g_norm_dst[r];
            v0.x = fmaf(v0.x, nd, bv0.x);
            v0.y = fmaf(v0.y, nd, bv0.y);
            v0.z = fmaf(v0.z, nd, bv0.z);
            v0.w = fmaf(v0.w, nd, bv0.w);
            v1.x = fmaf(v1.x, nd, bv1.x);
            v1.y = fmaf(v1.y, nd, bv1.y);
            v1.z = fmaf(v1.z, nd, bv1.z);
            v1.w = fmaf(v1.w, nd, bv1.w);
        }
        *(float4*)&O[r * DH + tx * 4]      = v0;
        *(float4*)&O[r * DH + tx * 4 + 64] = v1;
    }
}

// ---------------- launch ----------------
extern "C" void kernel_launch(void* const* d_in, const int* in_sizes, int n_in,
                              void* d_out, int out_size) {
    const float* in_feat = (const float*)d_in[0];
    const int*   src     = (const int*)d_in[1];
    const int*   dst     = (const int*)d_in[2];
    const float* W1      = (const float*)d_in[3];
    const float* b1      = (const float*)d_in[4];
    const float* gamma   = (const float*)d_in[5];
    const float* beta    = (const float*)d_in[6];
    const float* W2      = (const float*)d_in[7];
    const float* b2      = (const float*)d_in[8];
    const float* Wc      = (const float*)d_in[9];
    const float* bc      = (const float*)d_in[10];
    float* out = (float*)d_out;

    const int GEMM_GRID   = (NN + 127) / 128;  // 782
    const int GATHER_GRID = (NN + 7) / 8;      // 12500 (8 warps/block)

    // per-replay reset + slot-table build + norms
    k_zero<<<(NN + 255) / 256, 256>>>();
    k_build<<<(NE + 255) / 256, 256>>>(src, dst);
    k_norms<<<(NN + 255) / 256, 256>>>();

    // MLP: GEMM1 -> BN stats -> BN finalize -> GEMM2 (BN+ReLU fused on A, relu*norm_src epilogue, in-place)
    k_gemm<0><<<GEMM_GRID, 256>>>(in_feat, W1, b1, nullptr);
    k_colreduce<<<512, DH>>>();
    k_bnfin<<<1, DH>>>(gamma, beta);
    k_gemm<1><<<GEMM_GRID, 256>>>(nullptr, W2, b2, nullptr);

    // 3 propagation steps: gather (atomic-free) + rare-overflow fixup + fused GEMM
    for (int s = 0; s < 3; s++) {
        k_gather<<<GATHER_GRID, 256>>>();
        k_ovf<<<1, 256>>>(src, dst);
        if (s < 2)
            k_gemm<2><<<GEMM_GRID, 256>>>(nullptr, Wc, bc, nullptr);
        else
            k_gemm<3><<<GEMM_GRID, 256>>>(nullptr, Wc, bc, out);
    }
}

// round 13
// speedup vs baseline: 1.7438x; 1.1300x over previous
#include <cuda_runtime.h>

#define NN 100000
#define DH 128
#define NE 1600000
#define BN_EPS 1e-5f
#define SLOTS 48
#define OVF_CAP 8192

typedef unsigned long long u64;

// packed 2xfp32 FMA (Blackwell FFMA2): d = a*b + c per 32-bit lane
__device__ __forceinline__ u64 fma2(u64 a, u64 b, u64 c) {
    u64 d;
    asm("fma.rn.f32x2 %0, %1, %2, %3;" : "=l"(d) : "l"(a), "l"(b), "l"(c));
    return d;
}
__device__ __forceinline__ u64 splat2(float x) {
    u64 d;
    asm("mov.b64 %0, {%1, %1};" : "=l"(d) : "r"(__float_as_uint(x)));
    return d;
}
union Cvt { u64 u; float2 f; };

// ---------------- scratch (device globals; no allocation allowed) ----------------
__device__ __align__(128) float g_buf[NN * DH];
__device__ __align__(128) float g_agg[NN * DH];
__device__ __align__(128) int   g_slot[NN * SLOTS];
__device__ int   g_pos[NN];       // in-degree counter / slot cursor
__device__ int   g_outdeg[NN];
__device__ float g_norm_src[NN];
__device__ float g_norm_dst[NN];
__device__ float g_colsum[DH];
__device__ float g_colsq[DH];
__device__ float g_scale[DH];
__device__ float g_shift[DH];
__device__ int   g_ovf[OVF_CAP];
__device__ int   g_n_ovf;

// ---------------- small utility kernels ----------------
__global__ void k_zero() {
    int i = blockIdx.x * blockDim.x + threadIdx.x;
    if (i < NN) { g_outdeg[i] = 0; g_pos[i] = 0; }
    if (i < DH) { g_colsum[i] = 0.f; g_colsq[i] = 0.f; }
    if (i == 0) g_n_ovf = 0;
}

__global__ void k_build(const int* __restrict__ src, const int* __restrict__ dst) {
    int e = blockIdx.x * blockDim.x + threadIdx.x;
    if (e >= NE) return;
    int s = src[e];
    int d = dst[e];
    atomicAdd(&g_outdeg[s], 1);
    int p = atomicAdd(&g_pos[d], 1);
    if (p < SLOTS) {
        g_slot[d * SLOTS + p] = s;
    } else {
        int o = atomicAdd(&g_n_ovf, 1);
        if (o < OVF_CAP) g_ovf[o] = e;
    }
}

__global__ void k_norms() {
    int i = blockIdx.x * blockDim.x + threadIdx.x;
    if (i < NN) {
        g_norm_src[i] = rsqrtf(fmaxf((float)g_outdeg[i], 1.0f));
        g_norm_dst[i] = rsqrtf(fmaxf((float)g_pos[i], 1.0f));  // g_pos == indeg
    }
}

__global__ void k_bnfin(const float* __restrict__ gamma, const float* __restrict__ beta) {
    int c = threadIdx.x;  // 128 threads
    float mu  = g_colsum[c] * (1.0f / NN);
    float var = g_colsq[c] * (1.0f / NN) - mu * mu;
    float inv = rsqrtf(var + BN_EPS);
    float sc  = gamma[c] * inv;
    g_scale[c] = sc;
    g_shift[c] = beta[c] - mu * sc;
}

// ---------------- gather: warp per dst node, register accumulation, single store ----------------
__global__ void __launch_bounds__(256) k_gather() {
    int warp = (blockIdx.x * blockDim.x + threadIdx.x) >> 5;
    int lane = threadIdx.x & 31;
    if (warp >= NN) return;
    int n = g_pos[warp];
    if (n > SLOTS) n = SLOTS;
    const int* sl = &g_slot[warp * SLOTS];
    const float* bufl = g_buf + (lane * 4);
    float4 acc = make_float4(0.f, 0.f, 0.f, 0.f);
    int s_next = (n > 0) ? __ldg(&sl[0]) : 0;
    for (int j = 0; j < n; j++) {
        int s = s_next;
        if (j + 1 < n) s_next = __ldg(&sl[j + 1]);   // prefetch next index
        float4 v = *(const float4*)(bufl + s * DH);
        acc.x += v.x; acc.y += v.y; acc.z += v.z; acc.w += v.w;
    }
    *(float4*)&g_agg[warp * DH + lane * 4] = acc;
}

// apply rare overflow edges (deg > SLOTS) with vector reductions; almost always n==0
__global__ void k_ovf(const int* __restrict__ src, const int* __restrict__ dst) {
    int n = g_n_ovf;
    if (n > OVF_CAP) n = OVF_CAP;
    int warp = threadIdx.x >> 5;      // 8 warps, 1 block
    int lane = threadIdx.x & 31;
    int loff = lane * 4;
    for (int i = warp; i < n; i += 8) {
        int e = g_ovf[i];
        int s = __ldg(&src[e]);
        int d = __ldg(&dst[e]);
        float4 v = *(const float4*)&g_buf[s * DH + loff];
        float* p = &g_agg[d * DH + loff];
        asm volatile("red.global.add.v4.f32 [%0], {%1, %2, %3, %4};"
                     :: "l"(p), "f"(v.x), "f"(v.y), "f"(v.z), "f"(v.w)
                     : "memory");
    }
}

// ---------------- fused GEMM (M x 128 @ 128 x 128), tile 128x128, K-chunk 32 ----------------
// 256 threads, 8x8 micro-tile; inner loop uses packed fma.rn.f32x2 (FFMA2, 2x rate).
// MODE 0: out = A@B + bias -> g_buf; epilogue also accumulates BN column stats (sum, sumsq)
// MODE 1: A'=relu(A*scale_k+shift_k); out=relu(A'@B+bias)*norm_src[r]  A=g_buf -> g_buf (in-place)
// MODE 2: out = relu((A@B)*norm_dst[r] + bias) * norm_src[r]  A=g_agg -> g_buf
// MODE 3: out = (A@B)*norm_dst[r] + bias                      A=g_agg -> d_out
template <int MODE>
__global__ void __launch_bounds__(256, 2) k_gemm(const float* __restrict__ Ain,
                                                 const float* __restrict__ B,
                                                 const float* __restrict__ bias,
                                                 float* __restrict__ Oout) {
    __shared__ float AsT[32][132];   // [k][row], padded
    __shared__ float Bs[32][128];

    const float* A = (MODE == 0) ? Ain : (MODE == 1 ? g_buf : g_agg);
    float* O       = (MODE == 3) ? Oout : g_buf;

    int tid  = threadIdx.x;
    int tx   = tid & 15;   // col group: cols tx*4..+3 and tx*4+64..+67
    int ty   = tid >> 4;   // row group: rows ty*8..+7
    int row0 = blockIdx.x * 128;

    u64 acc2[8][4];        // 8 rows x 4 packed col-pairs (cols: tx*4+0/1, +2/3, +64/65, +66/67)
#pragma unroll
    for (int i = 0; i < 8; i++)
#pragma unroll
        for (int j = 0; j < 4; j++) acc2[i][j] = 0ULL;

    for (int k0 = 0; k0 < DH; k0 += 32) {
        // A tile: 128 rows x 32 k; f = t*256 + tid; r = f>>3 (0..127), k4 = f&7
#pragma unroll
        for (int t = 0; t < 4; t++) {
            int f  = t * 256 + tid;
            int r  = f >> 3;
            int k4 = f & 7;
            int gr = row0 + r;
            float4 a = (gr < NN) ? *(const float4*)&A[gr * DH + k0 + k4 * 4]
                                 : make_float4(0.f, 0.f, 0.f, 0.f);
            if (MODE == 1) {
                float4 sc = *(const float4*)&g_scale[k0 + k4 * 4];
                float4 sh = *(const float4*)&g_shift[k0 + k4 * 4];
                a.x = fmaxf(fmaf(a.x, sc.x, sh.x), 0.f);
                a.y = fmaxf(fmaf(a.y, sc.y, sh.y), 0.f);
                a.z = fmaxf(fmaf(a.z, sc.z, sh.z), 0.f);
                a.w = fmaxf(fmaf(a.w, sc.w, sh.w), 0.f);
            }
            AsT[k4 * 4 + 0][r] = a.x;
            AsT[k4 * 4 + 1][r] = a.y;
            AsT[k4 * 4 + 2][r] = a.z;
            AsT[k4 * 4 + 3][r] = a.w;
        }
        // B tile: 32 x 128; f = t*256 + tid; r = f>>5, c4 = f&31
#pragma unroll
        for (int t = 0; t < 4; t++) {
            int f  = t * 256 + tid;
            int r  = f >> 5;
            int c4 = f & 31;
            *(float4*)&Bs[r][c4 * 4] = *(const float4*)&B[(k0 + r) * DH + c4 * 4];
        }
        __syncthreads();

#pragma unroll
        for (int kk = 0; kk < 32; kk++) {
            float4 a0 = *(float4*)&AsT[kk][ty * 8];
            float4 a1 = *(float4*)&AsT[kk][ty * 8 + 4];
            // packed B pairs: 16B loads give 2 b64 pairs each
            ulonglong2 bb0 = *(const ulonglong2*)&Bs[kk][tx * 4];
            ulonglong2 bb1 = *(const ulonglong2*)&Bs[kk][tx * 4 + 64];
            u64 bv[4] = {bb0.x, bb0.y, bb1.x, bb1.y};
            float av[8] = {a0.x, a0.y, a0.z, a0.w, a1.x, a1.y, a1.z, a1.w};
#pragma unroll
            for (int i = 0; i < 8; i++) {
                u64 ai = splat2(av[i]);
#pragma unroll
                for (int j = 0; j < 4; j++)
                    acc2[i][j] = fma2(ai, bv[j], acc2[i][j]);
            }
        }
        __syncthreads();
    }

    float4 bv0 = *(const float4*)&bias[tx * 4];
    float4 bv1 = *(const float4*)&bias[tx * 4 + 64];
    float colp[8], colq[8];   // BN partial stats (MODE 0 only)
    if (MODE == 0) {
#pragma unroll
        for (int j = 0; j < 8; j++) { colp[j] = 0.f; colq[j] = 0.f; }
    }

#pragma unroll
    for (int i = 0; i < 8; i++) {
        int r = row0 + ty * 8 + i;
        if (r >= NN) break;
        Cvt c0, c1, c2, c3;
        c0.u = acc2[i][0]; c1.u = acc2[i][1]; c2.u = acc2[i][2]; c3.u = acc2[i][3];
        float4 v0 = make_float4(c0.f.x, c0.f.y, c1.f.x, c1.f.y);
        float4 v1 = make_float4(c2.f.x, c2.f.y, c3.f.x, c3.f.y);
        if (MODE == 0) {
            v0.x += bv0.x; v0.y += bv0.y; v0.z += bv0.z; v0.w += bv0.w;
            v1.x += bv1.x; v1.y += bv1.y; v1.z += bv1.z; v1.w += bv1.w;
            colp[0] += v0.x; colq[0] += v0.x * v0.x;
            colp[1] += v0.y; colq[1] += v0.y * v0.y;
            colp[2] += v0.z; colq[2] += v0.z * v0.z;
            colp[3] += v0.w; colq[3] += v0.w * v0.w;
            colp[4] += v1.x; colq[4] += v1.x * v1.x;
            colp[5] += v1.y; colq[5] += v1.y * v1.y;
            colp[6] += v1.z; colq[6] += v1.z * v1.z;
            colp[7] += v1.w; colq[7] += v1.w * v1.w;
        } else if (MODE == 1) {
            float ns = g_norm_src[r];
            v0.x = fmaxf(v0.x + bv0.x, 0.f) * ns;
            v0.y = fmaxf(v0.y + bv0.y, 0.f) * ns;
            v0.z = fmaxf(v0.z + bv0.z, 0.f) * ns;
            v0.w = fmaxf(v0.w + bv0.w, 0.f) * ns;
            v1.x = fmaxf(v1.x + bv1.x, 0.f) * ns;
            v1.y = fmaxf(v1.y + bv1.y, 0.f) * ns;
            v1.z = fmaxf(v1.z + bv1.z, 0.f) * ns;
            v1.w = fmaxf(v1.w + bv1.w, 0.f) * ns;
        } else if (MODE == 2) {
            float nd = g_norm_dst[r];
            float ns = g_norm_src[r];
            v0.x = fmaxf(fmaf(v0.x, nd, bv0.x), 0.f) * ns;
            v0.y = fmaxf(fmaf(v0.y, nd, bv0.y), 0.f) * ns;
            v0.z = fmaxf(fmaf(v0.z, nd, bv0.z), 0.f) * ns;
            v0.w = fmaxf(fmaf(v0.w, nd, bv0.w), 0.f) * ns;
            v1.x = fmaxf(fmaf(v1.x, nd, bv1.x), 0.f) * ns;
            v1.y = fmaxf(fmaf(v1.y, nd, bv1.y), 0.f) * ns;
            v1.z = fmaxf(fmaf(v1.z, nd, bv1.z), 0.f) * ns;
            v1.w = fmaxf(fmaf(v1.w, nd, bv1.w), 0.f) * ns;
        } else {  // MODE 3
            float nd = g_norm_dst[r];
            v0.x = fmaf(v0.x, nd, bv0.x);
            v0.y = fmaf(v0.y, nd, bv0.y);
            v0.z = fmaf(v0.z, nd, bv0.z);
            v0.w = fmaf(v0.w, nd, bv0.w);
            v1.x = fmaf(v1.x, nd, bv1.x);
            v1.y = fmaf(v1.y, nd, bv1.y);
            v1.z = fmaf(v1.z, nd, bv1.z);
            v1.w = fmaf(v1.w, nd, bv1.w);
        }
        *(float4*)&O[r * DH + tx * 4]      = v0;
        *(float4*)&O[r * DH + tx * 4 + 64] = v1;
    }

    if (MODE == 0) {
        // block-reduce BN stats via smem (Bs is dead after last sync), then 1 global atomic/col
        float* s_sum = (float*)Bs;            // [0..127] sum, [128..255] sumsq
        if (tid < 256) s_sum[tid] = 0.f;
        __syncthreads();
#pragma unroll
        for (int j = 0; j < 4; j++) {
            atomicAdd(&s_sum[tx * 4 + j], colp[j]);
            atomicAdd(&s_sum[tx * 4 + 64 + j], colp[4 + j]);
            atomicAdd(&s_sum[128 + tx * 4 + j], colq[j]);
            atomicAdd(&s_sum[128 + tx * 4 + 64 + j], colq[4 + j]);
        }
        __syncthreads();
        if (tid < 128) {
            atomicAdd(&g_colsum[tid], s_sum[tid]);
            atomicAdd(&g_colsq[tid], s_sum[128 + tid]);
        }
    }
}

// ---------------- launch ----------------
extern "C" void kernel_launch(void* const* d_in, const int* in_sizes, int n_in,
                              void* d_out, int out_size) {
    const float* in_feat = (const float*)d_in[0];
    const int*   src     = (const int*)d_in[1];
    const int*   dst     = (const int*)d_in[2];
    const float* W1      = (const float*)d_in[3];
    const float* b1      = (const float*)d_in[4];
    const float* gamma   = (const float*)d_in[5];
    const float* beta    = (const float*)d_in[6];
    const float* W2      = (const float*)d_in[7];
    const float* b2      = (const float*)d_in[8];
    const float* Wc      = (const float*)d_in[9];
    const float* bc      = (const float*)d_in[10];
    float* out = (float*)d_out;

    const int GEMM_GRID   = (NN + 127) / 128;  // 782
    const int GATHER_GRID = (NN + 7) / 8;      // 12500 (8 warps/block)

    // per-replay reset + slot-table build + norms
    k_zero<<<(NN + 255) / 256, 256>>>();
    k_build<<<(NE + 255) / 256, 256>>>(src, dst);
    k_norms<<<(NN + 255) / 256, 256>>>();

    // MLP: GEMM1 (BN stats fused in epilogue) -> BN finalize -> GEMM2 (BN+ReLU on A, in-place)
    k_gemm<0><<<GEMM_GRID, 256>>>(in_feat, W1, b1, nullptr);
    k_bnfin<<<1, DH>>>(gamma, beta);
    k_gemm<1><<<GEMM_GRID, 256>>>(nullptr, W2, b2, nullptr);

    // 3 propagation steps: gather (atomic-free) + rare-overflow fixup + fused GEMM
    for (int s = 0; s < 3; s++) {
        k_gather<<<GATHER_GRID, 256>>>();
        k_ovf<<<1, 256>>>(src, dst);
        if (s < 2)
            k_gemm<2><<<GEMM_GRID, 256>>>(nullptr, Wc, bc, nullptr);
        else
            k_gemm<3><<<GEMM_GRID, 256>>>(nullptr, Wc, bc, out);
    }
}